// round 8
// baseline (speedup 1.0000x reference)
#include <cuda_runtime.h>
#include <cuda_fp16.h>
#include <math.h>

#define NN 50000
#define NE 800000
#define NET (NE + NN)       // edges + self loops = 850000
#define HC 256              // H*C
#define NH 4
#define CC 64

// ---------------- scratch (static device globals; no allocs) ----------------
__device__ __align__(16) __half g_h[NN * HC];     // transformed features (fp16, per layer)
__device__ __align__(16) float g_x1[NN * HC];     // layer-0 activated output
__device__ __align__(16) float g_acc[NN * HC];    // layer-1 aggregation output
__device__ __align__(16) float g_asrc[NN * NH];
__device__ __align__(16) float g_adst[NN * NH];
__device__ int g_deg[NN];
__device__ int g_off[NN + 1];
__device__ int g_cur[NN];
__device__ int g_adj[NET];                        // src ids grouped by dst
__device__ int g_is64;

// ---------------- zero deg + detect edge dtype (fused) ----------------
__global__ void zerodetect_k(const int* ei32) {
    int i = blockIdx.x * blockDim.x + threadIdx.x;
    if (i < NN) g_deg[i] = 0;
    if (i == 0) {
        int ok = 1;
        #pragma unroll
        for (int k = 0; k < 64; k++)
            if (ei32[2 * k + 1] != 0) ok = 0;
        g_is64 = ok;
    }
}

__device__ __forceinline__ void edge_sd(const void* ei, int e, int& s, int& d) {
    if (e >= NE) { s = d = e - NE; return; }
    if (g_is64) {
        const long long* p = (const long long*)ei;
        s = (int)p[e];
        d = (int)p[NE + e];
    } else {
        const int* p = (const int*)ei;
        s = p[e];
        d = p[NE + e];
    }
}

// ---------------- CSR build ----------------
__global__ void hist_k(const void* __restrict__ ei) {
    int e = blockIdx.x * blockDim.x + threadIdx.x;
    if (e >= NET) return;
    int s, d;
    edge_sd(ei, e, s, d);
    atomicAdd(&g_deg[d], 1);
}

// single-block exclusive scan of g_deg[NN] -> g_off/g_cur (1024 threads, 2-pass)
#define SCHUNK 49   // 1024*49 = 50176 >= NN
__global__ __launch_bounds__(1024) void scanall_k() {
    __shared__ int wsum[32];
    const int t = threadIdx.x;
    const int lane = t & 31;
    const int wid = t >> 5;
    const int base = t * SCHUNK;

    int sum = 0;
    #pragma unroll 7
    for (int i = 0; i < SCHUNK; i++) {
        int idx = base + i;
        if (idx < NN) sum += g_deg[idx];
    }
    // hierarchical exclusive scan of per-thread sums
    int incl = sum;
    #pragma unroll
    for (int o = 1; o < 32; o <<= 1) {
        int x = __shfl_up_sync(0xffffffffu, incl, o);
        if (lane >= o) incl += x;
    }
    if (lane == 31) wsum[wid] = incl;
    __syncthreads();
    if (wid == 0) {
        int w = wsum[lane];
        int wi = w;
        #pragma unroll
        for (int o = 1; o < 32; o <<= 1) {
            int x = __shfl_up_sync(0xffffffffu, wi, o);
            if (lane >= o) wi += x;
        }
        wsum[lane] = wi - w;   // exclusive
    }
    __syncthreads();
    int run = incl - sum + wsum[wid];

    #pragma unroll 7
    for (int i = 0; i < SCHUNK; i++) {
        int idx = base + i;
        if (idx < NN) {
            g_off[idx] = run;
            g_cur[idx] = run;
            run += g_deg[idx];
        }
    }
    if (t == 1023) g_off[NN] = run;
}

__global__ void fill_k(const void* __restrict__ ei) {
    int e = blockIdx.x * blockDim.x + threadIdx.x;
    if (e >= NET) return;
    int s, d;
    edge_sd(ei, e, s, d);
    int p = atomicAdd(&g_cur[d], 1);
    g_adj[p] = s;
}

// ---------------- tensor-core GEMM (fp16 HMMA, fp32 accum) ----------------
// ALPHA: fp16 output + per-row alpha dots (head = blockIdx.x).
// FMAX:  A-element = max(A, A2 + ab); fp32 output with +bias (final projection).
#define APAD 40
#define BPAD 72
__device__ __forceinline__ unsigned su32(const void* p) {
    return (unsigned)__cvta_generic_to_shared(p);
}
__device__ __forceinline__ void ldm_x4(unsigned addr, unsigned& r0, unsigned& r1,
                                       unsigned& r2, unsigned& r3) {
    asm volatile("ldmatrix.sync.aligned.m8n8.x4.shared.b16 {%0,%1,%2,%3},[%4];"
                 : "=r"(r0), "=r"(r1), "=r"(r2), "=r"(r3) : "r"(addr));
}
__device__ __forceinline__ void ldm_x4t(unsigned addr, unsigned& r0, unsigned& r1,
                                        unsigned& r2, unsigned& r3) {
    asm volatile("ldmatrix.sync.aligned.m8n8.x4.trans.shared.b16 {%0,%1,%2,%3},[%4];"
                 : "=r"(r0), "=r"(r1), "=r"(r2), "=r"(r3) : "r"(addr));
}
__device__ __forceinline__ void mma16816(float& d0, float& d1, float& d2, float& d3,
                                         unsigned a0, unsigned a1, unsigned a2, unsigned a3,
                                         unsigned b0, unsigned b1) {
    asm volatile(
        "mma.sync.aligned.m16n8k16.row.col.f32.f16.f16.f32 "
        "{%0,%1,%2,%3},{%4,%5,%6,%7},{%8,%9},{%0,%1,%2,%3};"
        : "+f"(d0), "+f"(d1), "+f"(d2), "+f"(d3)
        : "r"(a0), "r"(a1), "r"(a2), "r"(a3), "r"(b0), "r"(b1));
}

template <bool ALPHA, bool FMAX>
__global__ __launch_bounds__(256) void gemm16_k(
    const float* __restrict__ A, const float* __restrict__ A2,
    const float* __restrict__ ab, const float* __restrict__ B,
    const float* __restrict__ bias,
    const float* __restrict__ aS, const float* __restrict__ aD,
    void* __restrict__ Cv, int M, int K, int Nc)
{
    __shared__ __half As[128][APAD];
    __shared__ __half Bs[32][BPAD];
    __shared__ float sPs[128];
    __shared__ float sPd[128];

    const int tid = threadIdx.x;
    const int lane = tid & 31;
    const int warp = tid >> 5;
    const int wm = warp & 3;
    const int wn = warp >> 2;
    const int m0 = blockIdx.y * 128;
    const int n0 = blockIdx.x * 64;

    float acc[2][4][4];
    #pragma unroll
    for (int mt = 0; mt < 2; mt++)
        #pragma unroll
        for (int nt = 0; nt < 4; nt++)
            #pragma unroll
            for (int r = 0; r < 4; r++) acc[mt][nt][r] = 0.f;

    if (ALPHA && tid < 128) { sPs[tid] = 0.f; sPd[tid] = 0.f; }

    float4 ra[4], rb[2], ran[4], rbn[2];

    auto load_frag = [&](int kt, float4 (&la)[4], float4 (&lb)[2]) {
        #pragma unroll
        for (int i = 0; i < 4; i++) {
            int q = tid + i * 256;
            int row = q >> 3;
            int ks = (q & 7) * 4;
            float4 v = make_float4(0.f, 0.f, 0.f, 0.f);
            if (m0 + row < M) {
                v = *(const float4*)(A + (size_t)(m0 + row) * K + kt + ks);
                if (FMAX) {
                    float4 v2 = *(const float4*)(A2 + (size_t)(m0 + row) * K + kt + ks);
                    float4 bb = *(const float4*)(ab + kt + ks);
                    v.x = fmaxf(v.x, v2.x + bb.x);
                    v.y = fmaxf(v.y, v2.y + bb.y);
                    v.z = fmaxf(v.z, v2.z + bb.z);
                    v.w = fmaxf(v.w, v2.w + bb.w);
                }
            }
            la[i] = v;
        }
        #pragma unroll
        for (int i = 0; i < 2; i++) {
            int q = tid + i * 256;
            int kr = q >> 4;
            int ns = (q & 15) * 4;
            lb[i] = *(const float4*)(B + (size_t)(kt + kr) * Nc + n0 + ns);
        }
    };
    auto store_frag = [&](const float4 (&la)[4], const float4 (&lb)[2]) {
        #pragma unroll
        for (int i = 0; i < 4; i++) {
            int q = tid + i * 256;
            int row = q >> 3;
            int ks = (q & 7) * 4;
            *(__half2*)&As[row][ks]     = __floats2half2_rn(la[i].x, la[i].y);
            *(__half2*)&As[row][ks + 2] = __floats2half2_rn(la[i].z, la[i].w);
        }
        #pragma unroll
        for (int i = 0; i < 2; i++) {
            int q = tid + i * 256;
            int kr = q >> 4;
            int ns = (q & 15) * 4;
            *(__half2*)&Bs[kr][ns]     = __floats2half2_rn(lb[i].x, lb[i].y);
            *(__half2*)&Bs[kr][ns + 2] = __floats2half2_rn(lb[i].z, lb[i].w);
        }
    };

    load_frag(0, ra, rb);

    for (int kt = 0; kt < K; kt += 32) {
        store_frag(ra, rb);
        __syncthreads();

        if (kt + 32 < K) load_frag(kt + 32, ran, rbn);

        #pragma unroll
        for (int kg = 0; kg < 2; kg++) {
            unsigned a[2][4], bq[2][4];
            #pragma unroll
            for (int mt = 0; mt < 2; mt++) {
                unsigned ad = su32(&As[wm * 32 + mt * 16 + (lane & 15)]
                                      [kg * 16 + (lane >> 4) * 8]);
                ldm_x4(ad, a[mt][0], a[mt][1], a[mt][2], a[mt][3]);
            }
            #pragma unroll
            for (int np = 0; np < 2; np++) {
                unsigned bd = su32(&Bs[kg * 16 + (lane & 15)]
                                      [wn * 32 + np * 16 + (lane >> 4) * 8]);
                ldm_x4t(bd, bq[np][0], bq[np][1], bq[np][2], bq[np][3]);
            }
            #pragma unroll
            for (int mt = 0; mt < 2; mt++)
                #pragma unroll
                for (int nt = 0; nt < 4; nt++) {
                    unsigned b0 = bq[nt >> 1][(nt & 1) * 2];
                    unsigned b1 = bq[nt >> 1][(nt & 1) * 2 + 1];
                    mma16816(acc[mt][nt][0], acc[mt][nt][1],
                             acc[mt][nt][2], acc[mt][nt][3],
                             a[mt][0], a[mt][1], a[mt][2], a[mt][3], b0, b1);
                }
        }
        __syncthreads();

        #pragma unroll
        for (int i = 0; i < 4; i++) ra[i] = ran[i];
        #pragma unroll
        for (int i = 0; i < 2; i++) rb[i] = rbn[i];
    }

    #pragma unroll
    for (int mt = 0; mt < 2; mt++) {
        int row0 = m0 + wm * 32 + mt * 16 + (lane >> 2);
        #pragma unroll
        for (int nt = 0; nt < 4; nt++) {
            int col = n0 + wn * 32 + nt * 8 + 2 * (lane & 3);
            if (ALPHA) {
                __half* C = (__half*)Cv;
                if (row0 < M)
                    *(__half2*)(C + (size_t)row0 * Nc + col) =
                        __floats2half2_rn(acc[mt][nt][0], acc[mt][nt][1]);
                if (row0 + 8 < M)
                    *(__half2*)(C + (size_t)(row0 + 8) * Nc + col) =
                        __floats2half2_rn(acc[mt][nt][2], acc[mt][nt][3]);
            } else {
                float* C = (float*)Cv;
                float2 bv = *(const float2*)(bias + col);
                if (row0 < M) {
                    float2 v = make_float2(acc[mt][nt][0] + bv.x, acc[mt][nt][1] + bv.y);
                    *(float2*)(C + (size_t)row0 * Nc + col) = v;
                }
                if (row0 + 8 < M) {
                    float2 v = make_float2(acc[mt][nt][2] + bv.x, acc[mt][nt][3] + bv.y);
                    *(float2*)(C + (size_t)(row0 + 8) * Nc + col) = v;
                }
            }
        }
    }

    if (ALPHA) {
        #pragma unroll
        for (int mt = 0; mt < 2; mt++) {
            float psg = 0.f, psg8 = 0.f, pdg = 0.f, pdg8 = 0.f;
            #pragma unroll
            for (int nt = 0; nt < 4; nt++) {
                int col = n0 + wn * 32 + nt * 8 + 2 * (lane & 3);
                float2 sv = *(const float2*)(aS + col);
                float2 dv = *(const float2*)(aD + col);
                psg  += acc[mt][nt][0] * sv.x + acc[mt][nt][1] * sv.y;
                psg8 += acc[mt][nt][2] * sv.x + acc[mt][nt][3] * sv.y;
                pdg  += acc[mt][nt][0] * dv.x + acc[mt][nt][1] * dv.y;
                pdg8 += acc[mt][nt][2] * dv.x + acc[mt][nt][3] * dv.y;
            }
            #pragma unroll
            for (int o = 1; o <= 2; o <<= 1) {
                psg  += __shfl_xor_sync(0xffffffffu, psg, o);
                psg8 += __shfl_xor_sync(0xffffffffu, psg8, o);
                pdg  += __shfl_xor_sync(0xffffffffu, pdg, o);
                pdg8 += __shfl_xor_sync(0xffffffffu, pdg8, o);
            }
            if ((lane & 3) == 0) {
                int rl = wm * 32 + mt * 16 + (lane >> 2);
                atomicAdd(&sPs[rl], psg);
                atomicAdd(&sPs[rl + 8], psg8);
                atomicAdd(&sPd[rl], pdg);
                atomicAdd(&sPd[rl + 8], pdg8);
            }
        }
        __syncthreads();
        if (tid < 128) {
            int row = m0 + tid;
            if (row < M) {
                int head = blockIdx.x;
                g_asrc[row * 4 + head] = sPs[tid];
                g_adst[row * 4 + head] = sPd[tid];
            }
        }
    }
}

// ---------------- fused edge-softmax + CSR gather (fp16 features) ----------------
// 2 warps per node (edge range split in half); 4 nodes per 256-thread block.
// Each lane: head = lane>>3, octet = lane&7 -> 8 channels. smem merge of halves.
// NOTE: NN % 4 == 0 so every block's 4 nodes are valid (no early-exit before sync).
template <bool ACT>
__global__ __launch_bounds__(256) void gather_k(
    const __half* __restrict__ h, float* __restrict__ out,
    const float* __restrict__ b0,
    const float* __restrict__ gamma,
    const float* __restrict__ beta)
{
    __shared__ float red[4][32][9];
    const int slot = threadIdx.x >> 6;          // 0..3 node slot
    const int node = blockIdx.x * 4 + slot;
    const int half = (threadIdx.x >> 5) & 1;    // warp of the pair
    const int lane = threadIdx.x & 31;
    const int head = lane >> 3;
    const int oct = lane & 7;

    const int o0 = g_off[node];
    const int o1 = g_off[node + 1];
    const int mid = o0 + ((o1 - o0 + 1) >> 1);
    int p = half ? mid : o0;
    const int end = half ? o1 : mid;

    const float ad = g_adst[node * 4 + head];
    float a[8];
    #pragma unroll
    for (int i = 0; i < 8; i++) a[i] = 0.f;
    float wsum = 0.f;

    const int coff = head * 64 + oct * 8;

    for (; p + 4 <= end; p += 4) {
        int s0 = g_adj[p + 0];
        int s1 = g_adj[p + 1];
        int s2 = g_adj[p + 2];
        int s3 = g_adj[p + 3];
        float e0 = g_asrc[s0 * 4 + head] + ad;
        float e1 = g_asrc[s1 * 4 + head] + ad;
        float e2 = g_asrc[s2 * 4 + head] + ad;
        float e3 = g_asrc[s3 * 4 + head] + ad;
        uint4 r0 = __ldcg((const uint4*)(h + (size_t)s0 * HC + coff));
        uint4 r1 = __ldcg((const uint4*)(h + (size_t)s1 * HC + coff));
        uint4 r2 = __ldcg((const uint4*)(h + (size_t)s2 * HC + coff));
        uint4 r3 = __ldcg((const uint4*)(h + (size_t)s3 * HC + coff));
        e0 = e0 > 0.f ? e0 : 0.2f * e0;
        e1 = e1 > 0.f ? e1 : 0.2f * e1;
        e2 = e2 > 0.f ? e2 : 0.2f * e2;
        e3 = e3 > 0.f ? e3 : 0.2f * e3;
        float w0 = __expf(e0), w1 = __expf(e1), w2 = __expf(e2), w3 = __expf(e3);
        wsum += (w0 + w1) + (w2 + w3);
        const uint4* rr[4] = {&r0, &r1, &r2, &r3};
        float ww[4] = {w0, w1, w2, w3};
        #pragma unroll
        for (int u = 0; u < 4; u++) {
            float2 f0 = __half22float2(*(const __half2*)&rr[u]->x);
            float2 f1 = __half22float2(*(const __half2*)&rr[u]->y);
            float2 f2 = __half22float2(*(const __half2*)&rr[u]->z);
            float2 f3 = __half22float2(*(const __half2*)&rr[u]->w);
            float w = ww[u];
            a[0] = fmaf(w, f0.x, a[0]);
            a[1] = fmaf(w, f0.y, a[1]);
            a[2] = fmaf(w, f1.x, a[2]);
            a[3] = fmaf(w, f1.y, a[3]);
            a[4] = fmaf(w, f2.x, a[4]);
            a[5] = fmaf(w, f2.y, a[5]);
            a[6] = fmaf(w, f3.x, a[6]);
            a[7] = fmaf(w, f3.y, a[7]);
        }
    }
    for (; p < end; p++) {
        int s = g_adj[p];
        float e = g_asrc[s * 4 + head] + ad;
        e = e > 0.f ? e : 0.2f * e;
        float w = __expf(e);
        uint4 raw = __ldcg((const uint4*)(h + (size_t)s * HC + coff));
        float2 f0 = __half22float2(*(__half2*)&raw.x);
        float2 f1 = __half22float2(*(__half2*)&raw.y);
        float2 f2 = __half22float2(*(__half2*)&raw.z);
        float2 f3 = __half22float2(*(__half2*)&raw.w);
        a[0] = fmaf(w, f0.x, a[0]);
        a[1] = fmaf(w, f0.y, a[1]);
        a[2] = fmaf(w, f1.x, a[2]);
        a[3] = fmaf(w, f1.y, a[3]);
        a[4] = fmaf(w, f2.x, a[4]);
        a[5] = fmaf(w, f2.y, a[5]);
        a[6] = fmaf(w, f3.x, a[6]);
        a[7] = fmaf(w, f3.y, a[7]);
        wsum += w;
    }

    // merge the two half-warps' partials
    if (half == 1) {
        #pragma unroll
        for (int i = 0; i < 8; i++) red[slot][lane][i] = a[i];
        red[slot][lane][8] = wsum;
    }
    __syncthreads();
    if (half == 1) return;

    #pragma unroll
    for (int i = 0; i < 8; i++) a[i] += red[slot][lane][i];
    wsum += red[slot][lane][8];

    float inv = 1.0f / (wsum + 1e-16f);
    #pragma unroll
    for (int i = 0; i < 8; i++) a[i] *= inv;

    float* op = out + (size_t)node * HC + coff;
    if (ACT) {
        const float r = rsqrtf(1.0f + 1e-5f);
        #pragma unroll
        for (int u = 0; u < 2; u++) {
            float4 bb = *(const float4*)(b0 + coff + u * 4);
            float4 gg = *(const float4*)(gamma + coff + u * 4);
            float4 be = *(const float4*)(beta + coff + u * 4);
            float v0 = (a[u * 4 + 0] + bb.x) * (gg.x * r) + be.x;
            float v1 = (a[u * 4 + 1] + bb.y) * (gg.y * r) + be.y;
            float v2 = (a[u * 4 + 2] + bb.z) * (gg.z * r) + be.z;
            float v3 = (a[u * 4 + 3] + bb.w) * (gg.w * r) + be.w;
            float4 o;
            o.x = v0 > 0.f ? v0 : expm1f(v0);
            o.y = v1 > 0.f ? v1 : expm1f(v1);
            o.z = v2 > 0.f ? v2 : expm1f(v2);
            o.w = v3 > 0.f ? v3 : expm1f(v3);
            *(float4*)(op + u * 4) = o;
        }
    } else {
        *(float4*)op = make_float4(a[0], a[1], a[2], a[3]);
        *(float4*)(op + 4) = make_float4(a[4], a[5], a[6], a[7]);
    }
}

// ---------------- launch ----------------
extern "C" void kernel_launch(void* const* d_in, const int* in_sizes, int n_in,
                              void* d_out, int out_size)
{
    const float* x      = (const float*)d_in[0];
    const void*  ei     = d_in[1];
    const float* W0     = (const float*)d_in[2];
    const float* as0    = (const float*)d_in[3];
    const float* ad0    = (const float*)d_in[4];
    const float* b0     = (const float*)d_in[5];
    const float* gamma0 = (const float*)d_in[6];
    const float* beta0  = (const float*)d_in[7];
    const float* W1     = (const float*)d_in[8];
    const float* as1    = (const float*)d_in[9];
    const float* ad1    = (const float*)d_in[10];
    const float* b1     = (const float*)d_in[11];
    const float* Wf     = (const float*)d_in[12];
    const float* bf     = (const float*)d_in[13];
    float* out = (float*)d_out;

    __half* h;
    float *x1, *acc;
    cudaGetSymbolAddress((void**)&h,   g_h);
    cudaGetSymbolAddress((void**)&x1,  g_x1);
    cudaGetSymbolAddress((void**)&acc, g_acc);

    static cudaStream_t s2 = nullptr;
    static cudaEvent_t evFork = nullptr, evJoin = nullptr;
    if (s2 == nullptr) {
        cudaStreamCreateWithFlags(&s2, cudaStreamNonBlocking);
        cudaEventCreateWithFlags(&evFork, cudaEventDisableTiming);
        cudaEventCreateWithFlags(&evJoin, cudaEventDisableTiming);
    }

    const int mb = (NN + 127) / 128;
    const int eb = (NET + 255) / 256;
    const int gb = NN / 4;   // NN % 4 == 0

    // ---- fork: CSR build on s2, concurrent with layer-0 GEMM ----
    cudaEventRecord(evFork, 0);
    cudaStreamWaitEvent(s2, evFork, 0);

    zerodetect_k<<<(NN + 255) / 256, 256, 0, s2>>>((const int*)ei);
    hist_k<<<eb, 256, 0, s2>>>(ei);
    scanall_k<<<1, 1024, 0, s2>>>();
    fill_k<<<eb, 256, 0, s2>>>(ei);
    cudaEventRecord(evJoin, s2);

    gemm16_k<true, false><<<dim3(HC / 64, mb), 256>>>(
        x, nullptr, nullptr, W0, nullptr, as0, ad0, h, NN, 128, HC);

    cudaStreamWaitEvent(0, evJoin, 0);

    gather_k<true><<<gb, 256>>>(h, x1, b0, gamma0, beta0);

    // ---- layer 1 ----
    gemm16_k<true, false><<<dim3(HC / 64, mb), 256>>>(
        x1, nullptr, nullptr, W1, nullptr, as1, ad1, h, NN, HC, HC);
    gather_k<false><<<gb, 256>>>(h, acc, nullptr, nullptr, nullptr);

    // ---- JK-max + final projection: out = max(x1, acc + b1) @ Wf + bf ----
    gemm16_k<false, true><<<dim3(1, mb), 256>>>(
        x1, acc, b1, Wf, bf, nullptr, nullptr, out, NN, HC, 64);
}

// round 9
// speedup vs baseline: 1.2839x; 1.2839x over previous
#include <cuda_runtime.h>
#include <cuda_fp16.h>
#include <math.h>

#define NN 50000
#define NE 800000
#define NET (NE + NN)       // edges + self loops = 850000
#define HC 256              // H*C
#define NH 4
#define CC 64
#define NB_SCAN 196         // ceil(NN/256)

// ---------------- scratch (static device globals; no allocs) ----------------
__device__ __align__(16) __half g_h[NN * HC];     // transformed features (fp16, per layer)
__device__ __align__(16) float g_x1[NN * HC];     // layer-0 activated output
__device__ __align__(16) float g_acc[NN * HC];    // layer-1 aggregation output
__device__ __align__(16) float g_asrc[NN * NH];
__device__ __align__(16) float g_adst[NN * NH];
__device__ int g_deg[NN];
__device__ int g_off[NN + 1];
__device__ int g_cur[NN];
__device__ int g_part[NB_SCAN];
__device__ int g_adj[NET];                        // src ids grouped by dst
__device__ int g_is64;

// ---------------- utility ----------------
__global__ void zeroi_k(int* p, int n) {
    int i = blockIdx.x * blockDim.x + threadIdx.x;
    if (i < n) p[i] = 0;
}

__global__ void detect_k(const int* ei32) {
    if (threadIdx.x == 0 && blockIdx.x == 0) {
        int ok = 1;
        #pragma unroll
        for (int k = 0; k < 64; k++)
            if (ei32[2 * k + 1] != 0) ok = 0;
        g_is64 = ok;
    }
}

__device__ __forceinline__ void edge_sd(const void* ei, int e, int& s, int& d) {
    if (e >= NE) { s = d = e - NE; return; }
    if (g_is64) {
        const long long* p = (const long long*)ei;
        s = (int)p[e];
        d = (int)p[NE + e];
    } else {
        const int* p = (const int*)ei;
        s = p[e];
        d = p[NE + e];
    }
}

// ---------------- CSR build ----------------
__global__ void hist_k(const void* __restrict__ ei) {
    int e = blockIdx.x * blockDim.x + threadIdx.x;
    if (e >= NET) return;
    int s, d;
    edge_sd(ei, e, s, d);
    atomicAdd(&g_deg[d], 1);
}

__global__ void scan1_k() {
    __shared__ int sh[256];
    int i = blockIdx.x * 256 + threadIdx.x;
    int v = (i < NN) ? g_deg[i] : 0;
    sh[threadIdx.x] = v; __syncthreads();
    for (int o = 128; o; o >>= 1) {
        if (threadIdx.x < o) sh[threadIdx.x] += sh[threadIdx.x + o];
        __syncthreads();
    }
    if (threadIdx.x == 0) g_part[blockIdx.x] = sh[0];
}

__global__ void scan2_k() {
    __shared__ int sh[256];
    int t = threadIdx.x;
    int v = (t < NB_SCAN) ? g_part[t] : 0;
    sh[t] = v; __syncthreads();
    for (int o = 1; o < 256; o <<= 1) {
        int x = (t >= o) ? sh[t - o] : 0;
        __syncthreads();
        sh[t] += x;
        __syncthreads();
    }
    if (t < NB_SCAN) g_part[t] = sh[t] - v;
}

__global__ void scan3_k() {
    __shared__ int sh[256];
    int t = threadIdx.x;
    int i = blockIdx.x * 256 + t;
    int v = (i < NN) ? g_deg[i] : 0;
    sh[t] = v; __syncthreads();
    for (int o = 1; o < 256; o <<= 1) {
        int x = (t >= o) ? sh[t - o] : 0;
        __syncthreads();
        sh[t] += x;
        __syncthreads();
    }
    if (i < NN) {
        int off = g_part[blockIdx.x] + sh[t] - v;
        g_off[i] = off;
        g_cur[i] = off;
        if (i == NN - 1) g_off[NN] = off + v;
    }
}

__global__ void fill_k(const void* __restrict__ ei) {
    int e = blockIdx.x * blockDim.x + threadIdx.x;
    if (e >= NET) return;
    int s, d;
    edge_sd(ei, e, s, d);
    int p = atomicAdd(&g_cur[d], 1);
    g_adj[p] = s;
}

// ---------------- tensor-core GEMM (fp16 HMMA, fp32 accum) ----------------
// ALPHA: fp16 output + per-row alpha dots (head = blockIdx.x).
// FMAX:  A-element = max(A, A2 + ab); fp32 output with +bias (final projection).
#define APAD 40
#define BPAD 72
__device__ __forceinline__ unsigned su32(const void* p) {
    return (unsigned)__cvta_generic_to_shared(p);
}
__device__ __forceinline__ void ldm_x4(unsigned addr, unsigned& r0, unsigned& r1,
                                       unsigned& r2, unsigned& r3) {
    asm volatile("ldmatrix.sync.aligned.m8n8.x4.shared.b16 {%0,%1,%2,%3},[%4];"
                 : "=r"(r0), "=r"(r1), "=r"(r2), "=r"(r3) : "r"(addr));
}
__device__ __forceinline__ void ldm_x4t(unsigned addr, unsigned& r0, unsigned& r1,
                                        unsigned& r2, unsigned& r3) {
    asm volatile("ldmatrix.sync.aligned.m8n8.x4.trans.shared.b16 {%0,%1,%2,%3},[%4];"
                 : "=r"(r0), "=r"(r1), "=r"(r2), "=r"(r3) : "r"(addr));
}
__device__ __forceinline__ void mma16816(float& d0, float& d1, float& d2, float& d3,
                                         unsigned a0, unsigned a1, unsigned a2, unsigned a3,
                                         unsigned b0, unsigned b1) {
    asm volatile(
        "mma.sync.aligned.m16n8k16.row.col.f32.f16.f16.f32 "
        "{%0,%1,%2,%3},{%4,%5,%6,%7},{%8,%9},{%0,%1,%2,%3};"
        : "+f"(d0), "+f"(d1), "+f"(d2), "+f"(d3)
        : "r"(a0), "r"(a1), "r"(a2), "r"(a3), "r"(b0), "r"(b1));
}

template <bool ALPHA, bool FMAX>
__global__ __launch_bounds__(256) void gemm16_k(
    const float* __restrict__ A, const float* __restrict__ A2,
    const float* __restrict__ ab, const float* __restrict__ B,
    const float* __restrict__ bias,
    const float* __restrict__ aS, const float* __restrict__ aD,
    void* __restrict__ Cv, int M, int K, int Nc)
{
    __shared__ __half As[128][APAD];
    __shared__ __half Bs[32][BPAD];
    __shared__ float sPs[128];
    __shared__ float sPd[128];

    const int tid = threadIdx.x;
    const int lane = tid & 31;
    const int warp = tid >> 5;
    const int wm = warp & 3;
    const int wn = warp >> 2;
    const int m0 = blockIdx.y * 128;
    const int n0 = blockIdx.x * 64;

    float acc[2][4][4];
    #pragma unroll
    for (int mt = 0; mt < 2; mt++)
        #pragma unroll
        for (int nt = 0; nt < 4; nt++)
            #pragma unroll
            for (int r = 0; r < 4; r++) acc[mt][nt][r] = 0.f;

    if (ALPHA && tid < 128) { sPs[tid] = 0.f; sPd[tid] = 0.f; }

    float4 ra[4], rb[2], ran[4], rbn[2];

    auto load_frag = [&](int kt, float4 (&la)[4], float4 (&lb)[2]) {
        #pragma unroll
        for (int i = 0; i < 4; i++) {
            int q = tid + i * 256;
            int row = q >> 3;
            int ks = (q & 7) * 4;
            float4 v = make_float4(0.f, 0.f, 0.f, 0.f);
            if (m0 + row < M) {
                v = *(const float4*)(A + (size_t)(m0 + row) * K + kt + ks);
                if (FMAX) {
                    float4 v2 = *(const float4*)(A2 + (size_t)(m0 + row) * K + kt + ks);
                    float4 bb = *(const float4*)(ab + kt + ks);
                    v.x = fmaxf(v.x, v2.x + bb.x);
                    v.y = fmaxf(v.y, v2.y + bb.y);
                    v.z = fmaxf(v.z, v2.z + bb.z);
                    v.w = fmaxf(v.w, v2.w + bb.w);
                }
            }
            la[i] = v;
        }
        #pragma unroll
        for (int i = 0; i < 2; i++) {
            int q = tid + i * 256;
            int kr = q >> 4;
            int ns = (q & 15) * 4;
            lb[i] = *(const float4*)(B + (size_t)(kt + kr) * Nc + n0 + ns);
        }
    };
    auto store_frag = [&](const float4 (&la)[4], const float4 (&lb)[2]) {
        #pragma unroll
        for (int i = 0; i < 4; i++) {
            int q = tid + i * 256;
            int row = q >> 3;
            int ks = (q & 7) * 4;
            *(__half2*)&As[row][ks]     = __floats2half2_rn(la[i].x, la[i].y);
            *(__half2*)&As[row][ks + 2] = __floats2half2_rn(la[i].z, la[i].w);
        }
        #pragma unroll
        for (int i = 0; i < 2; i++) {
            int q = tid + i * 256;
            int kr = q >> 4;
            int ns = (q & 15) * 4;
            *(__half2*)&Bs[kr][ns]     = __floats2half2_rn(lb[i].x, lb[i].y);
            *(__half2*)&Bs[kr][ns + 2] = __floats2half2_rn(lb[i].z, lb[i].w);
        }
    };

    load_frag(0, ra, rb);

    for (int kt = 0; kt < K; kt += 32) {
        store_frag(ra, rb);
        __syncthreads();

        if (kt + 32 < K) load_frag(kt + 32, ran, rbn);

        #pragma unroll
        for (int kg = 0; kg < 2; kg++) {
            unsigned a[2][4], bq[2][4];
            #pragma unroll
            for (int mt = 0; mt < 2; mt++) {
                unsigned ad = su32(&As[wm * 32 + mt * 16 + (lane & 15)]
                                      [kg * 16 + (lane >> 4) * 8]);
                ldm_x4(ad, a[mt][0], a[mt][1], a[mt][2], a[mt][3]);
            }
            #pragma unroll
            for (int np = 0; np < 2; np++) {
                unsigned bd = su32(&Bs[kg * 16 + (lane & 15)]
                                      [wn * 32 + np * 16 + (lane >> 4) * 8]);
                ldm_x4t(bd, bq[np][0], bq[np][1], bq[np][2], bq[np][3]);
            }
            #pragma unroll
            for (int mt = 0; mt < 2; mt++)
                #pragma unroll
                for (int nt = 0; nt < 4; nt++) {
                    unsigned b0 = bq[nt >> 1][(nt & 1) * 2];
                    unsigned b1 = bq[nt >> 1][(nt & 1) * 2 + 1];
                    mma16816(acc[mt][nt][0], acc[mt][nt][1],
                             acc[mt][nt][2], acc[mt][nt][3],
                             a[mt][0], a[mt][1], a[mt][2], a[mt][3], b0, b1);
                }
        }
        __syncthreads();

        #pragma unroll
        for (int i = 0; i < 4; i++) ra[i] = ran[i];
        #pragma unroll
        for (int i = 0; i < 2; i++) rb[i] = rbn[i];
    }

    #pragma unroll
    for (int mt = 0; mt < 2; mt++) {
        int row0 = m0 + wm * 32 + mt * 16 + (lane >> 2);
        #pragma unroll
        for (int nt = 0; nt < 4; nt++) {
            int col = n0 + wn * 32 + nt * 8 + 2 * (lane & 3);
            if (ALPHA) {
                __half* C = (__half*)Cv;
                if (row0 < M)
                    *(__half2*)(C + (size_t)row0 * Nc + col) =
                        __floats2half2_rn(acc[mt][nt][0], acc[mt][nt][1]);
                if (row0 + 8 < M)
                    *(__half2*)(C + (size_t)(row0 + 8) * Nc + col) =
                        __floats2half2_rn(acc[mt][nt][2], acc[mt][nt][3]);
            } else {
                float* C = (float*)Cv;
                float2 bv = *(const float2*)(bias + col);
                if (row0 < M) {
                    float2 v = make_float2(acc[mt][nt][0] + bv.x, acc[mt][nt][1] + bv.y);
                    *(float2*)(C + (size_t)row0 * Nc + col) = v;
                }
                if (row0 + 8 < M) {
                    float2 v = make_float2(acc[mt][nt][2] + bv.x, acc[mt][nt][3] + bv.y);
                    *(float2*)(C + (size_t)(row0 + 8) * Nc + col) = v;
                }
            }
        }
    }

    if (ALPHA) {
        #pragma unroll
        for (int mt = 0; mt < 2; mt++) {
            float psg = 0.f, psg8 = 0.f, pdg = 0.f, pdg8 = 0.f;
            #pragma unroll
            for (int nt = 0; nt < 4; nt++) {
                int col = n0 + wn * 32 + nt * 8 + 2 * (lane & 3);
                float2 sv = *(const float2*)(aS + col);
                float2 dv = *(const float2*)(aD + col);
                psg  += acc[mt][nt][0] * sv.x + acc[mt][nt][1] * sv.y;
                psg8 += acc[mt][nt][2] * sv.x + acc[mt][nt][3] * sv.y;
                pdg  += acc[mt][nt][0] * dv.x + acc[mt][nt][1] * dv.y;
                pdg8 += acc[mt][nt][2] * dv.x + acc[mt][nt][3] * dv.y;
            }
            #pragma unroll
            for (int o = 1; o <= 2; o <<= 1) {
                psg  += __shfl_xor_sync(0xffffffffu, psg, o);
                psg8 += __shfl_xor_sync(0xffffffffu, psg8, o);
                pdg  += __shfl_xor_sync(0xffffffffu, pdg, o);
                pdg8 += __shfl_xor_sync(0xffffffffu, pdg8, o);
            }
            if ((lane & 3) == 0) {
                int rl = wm * 32 + mt * 16 + (lane >> 2);
                atomicAdd(&sPs[rl], psg);
                atomicAdd(&sPs[rl + 8], psg8);
                atomicAdd(&sPd[rl], pdg);
                atomicAdd(&sPd[rl + 8], pdg8);
            }
        }
        __syncthreads();
        if (tid < 128) {
            int row = m0 + tid;
            if (row < M) {
                int head = blockIdx.x;
                g_asrc[row * 4 + head] = sPs[tid];
                g_adst[row * 4 + head] = sPd[tid];
            }
        }
    }
}

// ---------------- fused edge-softmax + CSR gather (fp16 features) ----------------
// ONE warp handles TWO nodes with interleaved edge chains (intra-warp MLP boost;
// no inter-warp sync). lane: head = lane>>3, octet = lane&7 -> 8 channels.
// 256-thread block = 8 warps = 16 nodes. NN % 16 == 0.
template <bool ACT>
__global__ __launch_bounds__(256) void gather_k(
    const __half* __restrict__ h, float* __restrict__ out,
    const float* __restrict__ b0,
    const float* __restrict__ gamma,
    const float* __restrict__ beta)
{
    const int warp = threadIdx.x >> 5;
    const int lane = threadIdx.x & 31;
    const int head = lane >> 3;
    const int oct = lane & 7;
    const int coff = head * 64 + oct * 8;

    const int nA = blockIdx.x * 16 + warp * 2;
    const int nB = nA + 1;
    int pA = g_off[nA];
    const int eA = g_off[nA + 1];
    int pB = g_off[nB];          // == eA, but keep general
    const int eB = g_off[nB + 1];

    const float adA = g_adst[nA * 4 + head];
    const float adB = g_adst[nB * 4 + head];
    float aA[8], aB[8];
    #pragma unroll
    for (int i = 0; i < 8; i++) { aA[i] = 0.f; aB[i] = 0.f; }
    float wsA = 0.f, wsB = 0.f;

    auto accum = [&](float w, const uint4& raw, float (&a)[8]) {
        float2 f0 = __half22float2(*(const __half2*)&raw.x);
        float2 f1 = __half22float2(*(const __half2*)&raw.y);
        float2 f2 = __half22float2(*(const __half2*)&raw.z);
        float2 f3 = __half22float2(*(const __half2*)&raw.w);
        a[0] = fmaf(w, f0.x, a[0]);
        a[1] = fmaf(w, f0.y, a[1]);
        a[2] = fmaf(w, f1.x, a[2]);
        a[3] = fmaf(w, f1.y, a[3]);
        a[4] = fmaf(w, f2.x, a[4]);
        a[5] = fmaf(w, f2.y, a[5]);
        a[6] = fmaf(w, f3.x, a[6]);
        a[7] = fmaf(w, f3.y, a[7]);
    };

    // interleaved main loop: 2 edges from A + 2 edges from B per iteration
    while (pA + 2 <= eA && pB + 2 <= eB) {
        int sA0 = g_adj[pA], sA1 = g_adj[pA + 1];
        int sB0 = g_adj[pB], sB1 = g_adj[pB + 1];
        float eAv0 = g_asrc[sA0 * 4 + head] + adA;
        float eAv1 = g_asrc[sA1 * 4 + head] + adA;
        float eBv0 = g_asrc[sB0 * 4 + head] + adB;
        float eBv1 = g_asrc[sB1 * 4 + head] + adB;
        uint4 rA0 = __ldcg((const uint4*)(h + (size_t)sA0 * HC + coff));
        uint4 rA1 = __ldcg((const uint4*)(h + (size_t)sA1 * HC + coff));
        uint4 rB0 = __ldcg((const uint4*)(h + (size_t)sB0 * HC + coff));
        uint4 rB1 = __ldcg((const uint4*)(h + (size_t)sB1 * HC + coff));
        eAv0 = eAv0 > 0.f ? eAv0 : 0.2f * eAv0;
        eAv1 = eAv1 > 0.f ? eAv1 : 0.2f * eAv1;
        eBv0 = eBv0 > 0.f ? eBv0 : 0.2f * eBv0;
        eBv1 = eBv1 > 0.f ? eBv1 : 0.2f * eBv1;
        float wA0 = __expf(eAv0), wA1 = __expf(eAv1);
        float wB0 = __expf(eBv0), wB1 = __expf(eBv1);
        wsA += wA0 + wA1;
        wsB += wB0 + wB1;
        accum(wA0, rA0, aA);
        accum(wA1, rA1, aA);
        accum(wB0, rB0, aB);
        accum(wB1, rB1, aB);
        pA += 2; pB += 2;
    }

    // drain remaining edges of one node (other exhausted below threshold)
    auto drain = [&](int p, int end, float ad, float (&a)[8], float& ws) {
        for (; p + 4 <= end; p += 4) {
            int s0 = g_adj[p + 0];
            int s1 = g_adj[p + 1];
            int s2 = g_adj[p + 2];
            int s3 = g_adj[p + 3];
            float e0 = g_asrc[s0 * 4 + head] + ad;
            float e1 = g_asrc[s1 * 4 + head] + ad;
            float e2 = g_asrc[s2 * 4 + head] + ad;
            float e3 = g_asrc[s3 * 4 + head] + ad;
            uint4 r0 = __ldcg((const uint4*)(h + (size_t)s0 * HC + coff));
            uint4 r1 = __ldcg((const uint4*)(h + (size_t)s1 * HC + coff));
            uint4 r2 = __ldcg((const uint4*)(h + (size_t)s2 * HC + coff));
            uint4 r3 = __ldcg((const uint4*)(h + (size_t)s3 * HC + coff));
            e0 = e0 > 0.f ? e0 : 0.2f * e0;
            e1 = e1 > 0.f ? e1 : 0.2f * e1;
            e2 = e2 > 0.f ? e2 : 0.2f * e2;
            e3 = e3 > 0.f ? e3 : 0.2f * e3;
            float w0 = __expf(e0), w1 = __expf(e1), w2 = __expf(e2), w3 = __expf(e3);
            ws += (w0 + w1) + (w2 + w3);
            accum(w0, r0, a);
            accum(w1, r1, a);
            accum(w2, r2, a);
            accum(w3, r3, a);
        }
        for (; p < end; p++) {
            int s = g_adj[p];
            float e = g_asrc[s * 4 + head] + ad;
            e = e > 0.f ? e : 0.2f * e;
            float w = __expf(e);
            uint4 raw = __ldcg((const uint4*)(h + (size_t)s * HC + coff));
            ws += w;
            accum(w, raw, a);
        }
    };
    drain(pA, eA, adA, aA, wsA);
    drain(pB, eB, adB, aB, wsB);

    auto emit = [&](int node, float (&a)[8], float ws) {
        float inv = 1.0f / (ws + 1e-16f);
        #pragma unroll
        for (int i = 0; i < 8; i++) a[i] *= inv;
        float* op = out + (size_t)node * HC + coff;
        if (ACT) {
            const float r = rsqrtf(1.0f + 1e-5f);
            #pragma unroll
            for (int u = 0; u < 2; u++) {
                float4 bb = *(const float4*)(b0 + coff + u * 4);
                float4 gg = *(const float4*)(gamma + coff + u * 4);
                float4 be = *(const float4*)(beta + coff + u * 4);
                float v0 = (a[u * 4 + 0] + bb.x) * (gg.x * r) + be.x;
                float v1 = (a[u * 4 + 1] + bb.y) * (gg.y * r) + be.y;
                float v2 = (a[u * 4 + 2] + bb.z) * (gg.z * r) + be.z;
                float v3 = (a[u * 4 + 3] + bb.w) * (gg.w * r) + be.w;
                float4 o;
                o.x = v0 > 0.f ? v0 : expm1f(v0);
                o.y = v1 > 0.f ? v1 : expm1f(v1);
                o.z = v2 > 0.f ? v2 : expm1f(v2);
                o.w = v3 > 0.f ? v3 : expm1f(v3);
                *(float4*)(op + u * 4) = o;
            }
        } else {
            *(float4*)op = make_float4(a[0], a[1], a[2], a[3]);
            *(float4*)(op + 4) = make_float4(a[4], a[5], a[6], a[7]);
        }
    };
    emit(nA, aA, wsA);
    emit(nB, aB, wsB);
}

// ---------------- launch ----------------
extern "C" void kernel_launch(void* const* d_in, const int* in_sizes, int n_in,
                              void* d_out, int out_size)
{
    const float* x      = (const float*)d_in[0];
    const void*  ei     = d_in[1];
    const float* W0     = (const float*)d_in[2];
    const float* as0    = (const float*)d_in[3];
    const float* ad0    = (const float*)d_in[4];
    const float* b0     = (const float*)d_in[5];
    const float* gamma0 = (const float*)d_in[6];
    const float* beta0  = (const float*)d_in[7];
    const float* W1     = (const float*)d_in[8];
    const float* as1    = (const float*)d_in[9];
    const float* ad1    = (const float*)d_in[10];
    const float* b1     = (const float*)d_in[11];
    const float* Wf     = (const float*)d_in[12];
    const float* bf     = (const float*)d_in[13];
    float* out = (float*)d_out;

    __half* h;
    float *x1, *acc;
    int* deg;
    cudaGetSymbolAddress((void**)&h,   g_h);
    cudaGetSymbolAddress((void**)&x1,  g_x1);
    cudaGetSymbolAddress((void**)&acc, g_acc);
    cudaGetSymbolAddress((void**)&deg, g_deg);

    static cudaStream_t s2 = nullptr;
    static cudaEvent_t evFork = nullptr, evJoin = nullptr;
    if (s2 == nullptr) {
        cudaStreamCreateWithFlags(&s2, cudaStreamNonBlocking);
        cudaEventCreateWithFlags(&evFork, cudaEventDisableTiming);
        cudaEventCreateWithFlags(&evJoin, cudaEventDisableTiming);
    }

    const int mb = (NN + 127) / 128;
    const int eb = (NET + 255) / 256;
    const int gb = NN / 16;   // NN % 16 == 0

    // ---- fork: CSR build on s2, concurrent with layer-0 GEMM ----
    cudaEventRecord(evFork, 0);
    cudaStreamWaitEvent(s2, evFork, 0);

    detect_k<<<1, 32, 0, s2>>>((const int*)ei);
    zeroi_k<<<(NN + 255) / 256, 256, 0, s2>>>(deg, NN);
    hist_k<<<eb, 256, 0, s2>>>(ei);
    scan1_k<<<NB_SCAN, 256, 0, s2>>>();
    scan2_k<<<1, 256, 0, s2>>>();
    scan3_k<<<NB_SCAN, 256, 0, s2>>>();
    fill_k<<<eb, 256, 0, s2>>>(ei);
    cudaEventRecord(evJoin, s2);

    gemm16_k<true, false><<<dim3(HC / 64, mb), 256>>>(
        x, nullptr, nullptr, W0, nullptr, as0, ad0, h, NN, 128, HC);

    cudaStreamWaitEvent(0, evJoin, 0);

    gather_k<true><<<gb, 256>>>(h, x1, b0, gamma0, beta0);

    // ---- layer 1 ----
    gemm16_k<true, false><<<dim3(HC / 64, mb), 256>>>(
        x1, nullptr, nullptr, W1, nullptr, as1, ad1, h, NN, HC, HC);
    gather_k<false><<<gb, 256>>>(h, acc, nullptr, nullptr, nullptr);

    // ---- JK-max + final projection: out = max(x1, acc + b1) @ Wf + bf ----
    gemm16_k<false, true><<<dim3(1, mb), 256>>>(
        x1, acc, b1, Wf, bf, nullptr, nullptr, out, NN, HC, 64);
}